// round 1
// baseline (speedup 1.0000x reference)
#include <cuda_runtime.h>
#include <math.h>

#define BB 8
#define CC 4
#define HH 512
#define WW 512
#define NPIX (HH*WW)
#define BIGI 1024   // H + W

// Scratch (device globals: allocation inside kernel_launch is forbidden)
static __device__ unsigned short d_g[2*BB*NPIX];   // 8 MB: column-pass distances
static __device__ float          d_g2[2*BB*NPIX];  // 16 MB: squared column distances
static __device__ float          d_dis[2*BB*NPIX]; // 16 MB: final EDT (pos, neg)
static __device__ int            d_minmax[2*BB*2]; // [pol*8+b][0]=min bits, [1]=max bits
static __device__ int            d_any[BB];
static __device__ double         d_acc;

__global__ void init_kernel() {
    int t = threadIdx.x;
    if (t < 2*BB) { d_minmax[2*t] = 0x7F800000; d_minmax[2*t+1] = 0; }
    if (t < BB) d_any[t] = 0;
    if (t == 0) d_acc = 0.0;
}

// One thread per (polarity, batch, column). Forward then backward 1D min-scan.
// g = min(prev+1, m ? BIG : 0) collapses the select+min into IADD+IMNMX chain.
__global__ void col_kernel(const float* __restrict__ yt) {
    int tid = blockIdx.x * blockDim.x + threadIdx.x;   // 8192 threads
    int pol = tid >> 12;
    int b   = (tid >> 9) & 7;
    int col = tid & 511;
    const float* src = yt + (size_t)(b*CC + 1) * NPIX + col;
    unsigned short* gp  = d_g  + (size_t)(pol*BB + b) * NPIX + col;
    float*          g2p = d_g2 + (size_t)(pol*BB + b) * NPIX + col;

    int prev = BIGI;
    int anyT = 0;
    #pragma unroll 8
    for (int i = 0; i < HH; i++) {
        float v = src[(size_t)i * WW];
        int ism = (v != 0.0f);          // mask pixel
        anyT |= ism;
        int mv = ((ism ^ pol) ? BIGI : 0);
        int g = min(prev + 1, mv);
        prev = g;
        gp[(size_t)i * WW] = (unsigned short)g;
    }
    if (pol == 0 && anyT) atomicOr(&d_any[b], 1);

    prev = BIGI;
    #pragma unroll 8
    for (int i = HH - 1; i >= 0; i--) {
        int g = (int)gp[(size_t)i * WW];
        g = min(g, prev + 1);
        prev = g;
        g2p[(size_t)i * WW] = (float)(g * g);
    }
}

// One block per row. Exact pruned parabola min:
// any candidate at radius r has value >= r^2, so stop once r^2 >= best.
__global__ void row_kernel() {
    __shared__ float s[WW];
    __shared__ float redmin[16], redmax[16];
    int base = blockIdx.x * WW;
    int j = threadIdx.x;
    float g2 = d_g2[base + j];
    s[j] = g2;
    __syncthreads();

    float best = g2;
    for (int r = 1; r < WW; r++) {
        float r2 = (float)(r * r);
        if (r2 >= best) break;
        if (j >= r)      best = fminf(best, s[j - r] + r2);
        if (j + r < WW)  best = fminf(best, s[j + r] + r2);
    }
    float dis = sqrtf(best);
    d_dis[base + j] = dis;

    // block min/max -> per-image atomics (float bits, all values >= 0)
    float mn = dis, mx = dis;
    #pragma unroll
    for (int o = 16; o; o >>= 1) {
        mn = fminf(mn, __shfl_xor_sync(0xffffffffu, mn, o));
        mx = fmaxf(mx, __shfl_xor_sync(0xffffffffu, mx, o));
    }
    int lane = j & 31, w = j >> 5;
    if (lane == 0) { redmin[w] = mn; redmax[w] = mx; }
    __syncthreads();
    if (j < 16) {
        mn = redmin[j]; mx = redmax[j];
        #pragma unroll
        for (int o = 8; o; o >>= 1) {
            mn = fminf(mn, __shfl_xor_sync(0xffffu, mn, o));
            mx = fmaxf(mx, __shfl_xor_sync(0xffffu, mx, o));
        }
        if (j == 0) {
            int pb = blockIdx.x >> 9;   // pol*8 + b
            atomicMin(&d_minmax[pb*2],     __float_as_int(mn));
            atomicMax(&d_minmax[pb*2 + 1], __float_as_int(mx));
        }
    }
}

// Fused: normalize -> boundary-zero -> sigmoid-sum product -> reduce
__global__ void accum_kernel(const float* __restrict__ yp,
                             const float* __restrict__ yt) {
    int idx0   = blockIdx.x * blockDim.x + threadIdx.x;
    int stride = gridDim.x * blockDim.x;
    float acc = 0.0f;
    for (int idx = idx0; idx < BB * NPIX; idx += stride) {
        int b  = idx >> 18;
        int ij = idx & (NPIX - 1);
        float term = 0.0f;
        if (d_any[b]) {
            float pos = d_dis[(size_t)b * NPIX + ij];
            float neg = d_dis[(size_t)(BB + b) * NPIX + ij];
            float pmin = __int_as_float(d_minmax[b*2]);
            float pmax = __int_as_float(d_minmax[b*2 + 1]);
            float nmin = __int_as_float(d_minmax[(BB + b)*2]);
            float nmax = __int_as_float(d_minmax[(BB + b)*2 + 1]);
            float sdf = (neg - nmin) / (nmax - nmin)
                      - (pos - pmin) / (pmax - pmin);

            const float* m = yt + (size_t)(b*CC + 1) * NPIX;
            int i = ij >> 9, j = ij & 511;
            if (m[ij] != 0.0f) {
                bool bd = false;
                if (i > 0)      bd |= (m[ij - WW] == 0.0f);
                if (i < HH - 1) bd |= (m[ij + WW] == 0.0f);
                if (j > 0)      bd |= (m[ij - 1]  == 0.0f);
                if (j < WW - 1) bd |= (m[ij + 1]  == 0.0f);
                if (bd) sdf = 0.0f;
            }
            float ssum = 0.0f;
            #pragma unroll
            for (int ch = 0; ch < CC; ch++) {
                float x = yp[((size_t)(b*CC + ch) << 18) + ij];
                ssum += 1.0f / (1.0f + expf(-x));
            }
            term = sdf * ssum;
        }
        acc += term;
    }
    #pragma unroll
    for (int o = 16; o; o >>= 1) acc += __shfl_xor_sync(0xffffffffu, acc, o);
    if ((threadIdx.x & 31) == 0) atomicAdd(&d_acc, (double)acc);
}

__global__ void fin_kernel(float* out) {
    out[0] = (float)(d_acc / (double)((size_t)BB * CC * NPIX));
}

extern "C" void kernel_launch(void* const* d_in, const int* in_sizes, int n_in,
                              void* d_out, int out_size) {
    const float* yp = (const float*)d_in[0];  // y_pred (8,4,512,512)
    const float* yt = (const float*)d_in[1];  // y_true (8,4,512,512)
    (void)in_sizes; (void)n_in; (void)out_size;

    init_kernel<<<1, 64>>>();
    col_kernel<<<(2*BB*WW) / 256, 256>>>(yt);
    row_kernel<<<2*BB*HH, WW>>>();
    accum_kernel<<<2048, 256>>>(yp, (const float*)d_in[1]);
    fin_kernel<<<1, 1>>>((float*)d_out);
}

// round 2
// speedup vs baseline: 2.7389x; 2.7389x over previous
#include <cuda_runtime.h>
#include <math.h>

#define BB 8
#define CC 4
#define HH 512
#define WW 512
#define NPIX (HH*WW)
#define BIGI 1024

// Scratch (device globals; allocation in kernel_launch is forbidden)
static __device__ unsigned int d_gp[BB*NPIX];     // packed col-pass g: pol0 lo16, pol1 hi16 (8 MB)
static __device__ float2       d_dis2[BB*NPIX];   // {pos^2, neg^2} per pixel (16 MB)
static __device__ int          d_minmax[BB*4];    // per b: pmin2,pmax2,nmin2,nmax2 (float bits)
static __device__ double       d_acc;             // zero-init; self-reset by accum last block
static __device__ int          d_count;           // zero-init; self-reset by accum last block

// ---------------------------------------------------------------------------
// Column pass: one thread per (b, col); both polarities fused (one y_true read).
// Forward min-plus scan then in-place backward scan on the packed array.
// Block 0 also initializes d_minmax (only read later, by row_kernel).
// ---------------------------------------------------------------------------
__global__ void col_kernel(const float* __restrict__ yt) {
    if (blockIdx.x == 0 && threadIdx.x < BB*4) {
        // even slots = mins (+inf bits), odd slots = maxs (0)
        d_minmax[threadIdx.x] = (threadIdx.x & 1) ? 0 : 0x7F800000;
    }
    int tid = blockIdx.x * blockDim.x + threadIdx.x;   // 4096 threads
    int b   = tid >> 9;
    int col = tid & 511;
    const float* src = yt + (size_t)(b*CC + 1) * NPIX + col;
    unsigned int* gp = d_gp + (size_t)b * NPIX + col;

    int p0 = BIGI, p1 = BIGI;
    #pragma unroll 16
    for (int i = 0; i < HH; i++) {
        float v = __ldg(src + (size_t)i * WW);
        int ism = (v != 0.0f);
        int m0 = ism ? BIGI : 0;     // edt(mask):  False pixels are sources
        int m1 = ism ? 0 : BIGI;     // edt(~mask): True pixels are sources
        p0 = min(p0 + 1, m0);
        p1 = min(p1 + 1, m1);
        gp[(size_t)i * WW] = (unsigned int)p0 | ((unsigned int)p1 << 16);
    }
    p0 = BIGI; p1 = BIGI;
    #pragma unroll 16
    for (int i = HH - 1; i >= 0; i--) {
        unsigned int g = gp[(size_t)i * WW];
        int g0 = (int)(g & 0xFFFFu);
        int g1 = (int)(g >> 16);
        g0 = min(g0, p0 + 1);
        g1 = min(g1, p1 + 1);
        p0 = g0; p1 = g1;
        gp[(size_t)i * WW] = (unsigned int)g0 | ((unsigned int)g1 << 16);
    }
}

// ---------------------------------------------------------------------------
// Row pass: one block per (b, row), both polarities. Exact pruned parabola min:
// any candidate at radius r contributes >= r^2, so stop once r^2 >= best.
// Tracks per-image min/max of d^2 (sqrt is monotone; extremes sqrt'd later).
// ---------------------------------------------------------------------------
__global__ void row_kernel() {
    __shared__ float s0[WW], s1[WW];
    __shared__ float red[4][16];
    int b   = blockIdx.x >> 9;
    int row = blockIdx.x & 511;
    int j   = threadIdx.x;
    size_t base = (size_t)b * NPIX + (size_t)row * WW;

    unsigned int g = d_gp[base + j];
    int g0 = (int)(g & 0xFFFFu);
    int g1 = (int)(g >> 16);
    float a0 = (float)(g0 * g0);
    float a1 = (float)(g1 * g1);
    s0[j] = a0; s1[j] = a1;
    __syncthreads();

    float best0 = a0, best1 = a1;
    for (int r = 1; r < WW; r++) {
        float r2 = (float)(r * r);
        if (r2 >= best0) break;
        if (j >= r)     best0 = fminf(best0, s0[j - r] + r2);
        if (j + r < WW) best0 = fminf(best0, s0[j + r] + r2);
    }
    for (int r = 1; r < WW; r++) {
        float r2 = (float)(r * r);
        if (r2 >= best1) break;
        if (j >= r)     best1 = fminf(best1, s1[j - r] + r2);
        if (j + r < WW) best1 = fminf(best1, s1[j + r] + r2);
    }
    d_dis2[base + j] = make_float2(best0, best1);

    // block min/max of best0/best1 -> 4 atomics (float bits, all >= 0)
    float v[4] = {best0, best0, best1, best1};
    #pragma unroll
    for (int o = 16; o; o >>= 1) {
        v[0] = fminf(v[0], __shfl_xor_sync(0xffffffffu, v[0], o));
        v[1] = fmaxf(v[1], __shfl_xor_sync(0xffffffffu, v[1], o));
        v[2] = fminf(v[2], __shfl_xor_sync(0xffffffffu, v[2], o));
        v[3] = fmaxf(v[3], __shfl_xor_sync(0xffffffffu, v[3], o));
    }
    int lane = j & 31, w = j >> 5;
    if (lane == 0) {
        red[0][w] = v[0]; red[1][w] = v[1]; red[2][w] = v[2]; red[3][w] = v[3];
    }
    __syncthreads();
    if (j < 16) {
        float mn0 = red[0][j], mx0 = red[1][j], mn1 = red[2][j], mx1 = red[3][j];
        #pragma unroll
        for (int o = 8; o; o >>= 1) {
            mn0 = fminf(mn0, __shfl_xor_sync(0xffffu, mn0, o));
            mx0 = fmaxf(mx0, __shfl_xor_sync(0xffffu, mx0, o));
            mn1 = fminf(mn1, __shfl_xor_sync(0xffffu, mn1, o));
            mx1 = fmaxf(mx1, __shfl_xor_sync(0xffffu, mx1, o));
        }
        if (j == 0) {
            atomicMin(&d_minmax[b*4 + 0], __float_as_int(mn0));
            atomicMax(&d_minmax[b*4 + 1], __float_as_int(mx0));
            atomicMin(&d_minmax[b*4 + 2], __float_as_int(mn1));
            atomicMax(&d_minmax[b*4 + 3], __float_as_int(mx1));
        }
    }
}

// ---------------------------------------------------------------------------
// Accumulate: sdf normalize + boundary (pos^2==1) + sigmoid-sum product.
// Grid (NPIX/1024, BB); 256 threads x 4 pixels. Last block finalizes + resets.
// ---------------------------------------------------------------------------
__device__ __forceinline__ float sigf(float x) {
    return __fdividef(1.0f, 1.0f + __expf(-x));
}

__global__ void accum_kernel(const float* __restrict__ yp, float* __restrict__ out) {
    __shared__ float sred[8];
    int b = blockIdx.y;
    float pmin2 = __int_as_float(d_minmax[b*4 + 0]);
    float pmax2 = __int_as_float(d_minmax[b*4 + 1]);
    float nmin2 = __int_as_float(d_minmax[b*4 + 2]);
    float nmax2 = __int_as_float(d_minmax[b*4 + 3]);
    bool any = (pmax2 > 0.0f);   // mask nonempty <=> some pixel has posdis >= 1

    float acc = 0.0f;
    if (any) {
        float pmin = sqrtf(pmin2), pmax = sqrtf(pmax2);
        float nmin = sqrtf(nmin2), nmax = sqrtf(nmax2);
        float pr = 1.0f / (pmax - pmin);
        float nr = 1.0f / (nmax - nmin);
        float cst = pmin * pr - nmin * nr;

        int pix0 = (blockIdx.x * blockDim.x + threadIdx.x) * 4;
        const float4* dp = (const float4*)(d_dis2 + (size_t)b * NPIX + pix0);
        float4 dA = __ldg(dp);       // {p0,n0,p1,n1}
        float4 dB = __ldg(dp + 1);   // {p2,n2,p3,n3}

        float sdf0 = (dA.x == 1.0f) ? 0.0f : (sqrtf(dA.y)*nr - sqrtf(dA.x)*pr + cst);
        float sdf1 = (dA.z == 1.0f) ? 0.0f : (sqrtf(dA.w)*nr - sqrtf(dA.z)*pr + cst);
        float sdf2 = (dB.x == 1.0f) ? 0.0f : (sqrtf(dB.y)*nr - sqrtf(dB.x)*pr + cst);
        float sdf3 = (dB.z == 1.0f) ? 0.0f : (sqrtf(dB.w)*nr - sqrtf(dB.z)*pr + cst);

        float s0 = 0.f, s1 = 0.f, s2 = 0.f, s3 = 0.f;
        #pragma unroll
        for (int ch = 0; ch < CC; ch++) {
            const float4* ypp = (const float4*)(yp + ((size_t)(b*CC + ch) << 18) + pix0);
            float4 y = __ldg(ypp);
            s0 += sigf(y.x); s1 += sigf(y.y); s2 += sigf(y.z); s3 += sigf(y.w);
        }
        acc = sdf0*s0 + sdf1*s1 + sdf2*s2 + sdf3*s3;
    }

    // block reduction
    #pragma unroll
    for (int o = 16; o; o >>= 1) acc += __shfl_xor_sync(0xffffffffu, acc, o);
    int lane = threadIdx.x & 31, w = threadIdx.x >> 5;
    if (lane == 0) sred[w] = acc;
    __syncthreads();
    if (threadIdx.x == 0) {
        float ba = 0.0f;
        #pragma unroll
        for (int k = 0; k < 8; k++) ba += sred[k];
        atomicAdd(&d_acc, (double)ba);
        __threadfence();
        int old = atomicAdd(&d_count, 1);
        int total = gridDim.x * gridDim.y;
        if (old == total - 1) {
            double t = atomicAdd(&d_acc, 0.0);  // coherent read of full sum
            out[0] = (float)(t / (double)((size_t)BB * CC * NPIX));
            d_acc = 0.0;      // self-reset for next launch/replay
            d_count = 0;
        }
    }
}

extern "C" void kernel_launch(void* const* d_in, const int* in_sizes, int n_in,
                              void* d_out, int out_size) {
    const float* yp = (const float*)d_in[0];  // y_pred (8,4,512,512)
    const float* yt = (const float*)d_in[1];  // y_true (8,4,512,512)
    (void)in_sizes; (void)n_in; (void)out_size;

    col_kernel<<<(BB*WW)/256, 256>>>(yt);
    row_kernel<<<BB*HH, WW>>>();
    accum_kernel<<<dim3(NPIX/1024, BB), 256>>>(yp, (float*)d_out);
}

// round 4
// speedup vs baseline: 4.0591x; 1.4820x over previous
#include <cuda_runtime.h>
#include <math.h>

#define BB 8
#define CC 4
#define HH 512
#define WW 512
#define NPIX (HH*WW)
#define BIGI 1024

#define SEG  8          // rows per thread in col pass
#define NSEG 64         // segments per column (SEG*NSEG == HH)
#define CPB  16         // columns per block (CPB*NSEG == 1024 threads)

// Scratch (device globals; allocation in kernel_launch is forbidden)
static __device__ unsigned int d_gp[BB*NPIX];     // packed col-pass g: pol0 lo16, pol1 hi16 (8 MB)
static __device__ float2       d_dis2[BB*NPIX];   // {pos^2, neg^2} per pixel (16 MB)
static __device__ int          d_minmax[BB*4];    // per b: pmin2,pmax2,nmin2,nmax2 (float bits)
static __device__ double       d_acc;             // zero-init; self-reset by accum last block
static __device__ int          d_count;

// ---------------------------------------------------------------------------
// Column pass, segmented scan formulation:
//   g[i] = min( i + prefmin_{j<=i}(m[j]-j),  -i + sufmin_{j>=i}(m[j]+j) )
// Each thread owns (b, col, 8-row segment). Segment mins combine through smem
// as scalar carries (prefix/suffix min is fully associative), so all 262144
// threads run in parallel instead of 4096 threads x 1024 serial steps.
// ---------------------------------------------------------------------------
__global__ void __launch_bounds__(CPB*NSEG) col_kernel(const float* __restrict__ yt) {
    if (blockIdx.x == 0 && threadIdx.x < BB*4)
        d_minmax[threadIdx.x] = (threadIdx.x & 1) ? 0 : 0x7F800000;

    __shared__ int sA0[NSEG][CPB], sB0[NSEG][CPB], sA1[NSEG][CPB], sB1[NSEG][CPB];

    int b   = blockIdx.x >> 5;                       // 32 col-tiles per batch
    int c   = threadIdx.x & (CPB-1);
    int col = ((blockIdx.x & 31) * CPB) + c;
    int seg = threadIdx.x / CPB;
    int r0  = seg * SEG;

    const float* src = yt + ((size_t)(b*CC + 1) << 18) + col;

    // Phase 1: read 8 rows once; mask -> bit register; segment mins of
    // (m-j) and (m+j) for both polarities.
    unsigned mb = 0;
    int A0 = 1<<28, B0 = 1<<28, A1 = 1<<28, B1 = 1<<28;
    #pragma unroll
    for (int j = 0; j < SEG; j++) {
        int r = r0 + j;
        float v = __ldg(src + (size_t)r * WW);
        int ism = (v != 0.0f);
        mb |= (unsigned)ism << j;
        int m0 = ism ? BIGI : 0;     // edt(mask)
        int m1 = ism ? 0 : BIGI;     // edt(~mask)
        A0 = min(A0, m0 - r);  B0 = min(B0, m0 + r);
        A1 = min(A1, m1 - r);  B1 = min(B1, m1 + r);
    }
    sA0[seg][c] = A0; sB0[seg][c] = B0; sA1[seg][c] = A1; sB1[seg][c] = B1;
    __syncthreads();

    // Scalar carries: prefix over earlier segments, suffix over later ones.
    int cA0 = 1<<28, cA1 = 1<<28, cB0 = 1<<28, cB1 = 1<<28;
    for (int s = 0; s < seg; s++)      { cA0 = min(cA0, sA0[s][c]); cA1 = min(cA1, sA1[s][c]); }
    for (int s = seg+1; s < NSEG; s++) { cB0 = min(cB0, sB0[s][c]); cB1 = min(cB1, sB1[s][c]); }

    // Phase 2: forward (prefix) part from the mask bits, kept in registers.
    unsigned freg[SEG];
    int rA0 = cA0, rA1 = cA1;
    #pragma unroll
    for (int j = 0; j < SEG; j++) {
        int r = r0 + j;
        int ism = (mb >> j) & 1;
        int m0 = ism ? BIGI : 0;
        int m1 = ism ? 0 : BIGI;
        rA0 = min(rA0, m0 - r);
        rA1 = min(rA1, m1 - r);
        freg[j] = (unsigned)(r + rA0) | ((unsigned)(r + rA1) << 16);
    }

    // Phase 3: backward (suffix) part; combine and store packed g once.
    unsigned* gp = d_gp + (size_t)b * NPIX + col;
    int rB0 = cB0, rB1 = cB1;
    #pragma unroll
    for (int j = SEG-1; j >= 0; j--) {
        int r = r0 + j;
        int ism = (mb >> j) & 1;
        int m0 = ism ? BIGI : 0;
        int m1 = ism ? 0 : BIGI;
        rB0 = min(rB0, m0 + r);
        rB1 = min(rB1, m1 + r);
        int g0 = min((int)(freg[j] & 0xFFFFu), rB0 - r);
        int g1 = min((int)(freg[j] >> 16),     rB1 - r);
        gp[(size_t)r * WW] = (unsigned)g0 | ((unsigned)g1 << 16);
    }
}

// ---------------------------------------------------------------------------
// Row pass: one block per (b, row), both polarities. Exact pruned parabola min:
// any candidate at radius r contributes >= r^2, so stop once r^2 >= best.
// ---------------------------------------------------------------------------
__global__ void row_kernel() {
    __shared__ float s0[WW], s1[WW];
    __shared__ float red[4][16];
    int b   = blockIdx.x >> 9;
    int row = blockIdx.x & 511;
    int j   = threadIdx.x;
    size_t base = (size_t)b * NPIX + (size_t)row * WW;

    unsigned int g = d_gp[base + j];
    int g0 = (int)(g & 0xFFFFu);
    int g1 = (int)(g >> 16);
    float a0 = (float)(g0 * g0);
    float a1 = (float)(g1 * g1);
    s0[j] = a0; s1[j] = a1;
    __syncthreads();

    float best0 = a0, best1 = a1;
    for (int r = 1; r < WW; r++) {
        float r2 = (float)(r * r);
        if (r2 >= best0) break;
        if (j >= r)     best0 = fminf(best0, s0[j - r] + r2);
        if (j + r < WW) best0 = fminf(best0, s0[j + r] + r2);
    }
    for (int r = 1; r < WW; r++) {
        float r2 = (float)(r * r);
        if (r2 >= best1) break;
        if (j >= r)     best1 = fminf(best1, s1[j - r] + r2);
        if (j + r < WW) best1 = fminf(best1, s1[j + r] + r2);
    }
    d_dis2[base + j] = make_float2(best0, best1);

    float v0 = best0, v1 = best0, v2 = best1, v3 = best1;
    #pragma unroll
    for (int o = 16; o; o >>= 1) {
        v0 = fminf(v0, __shfl_xor_sync(0xffffffffu, v0, o));
        v1 = fmaxf(v1, __shfl_xor_sync(0xffffffffu, v1, o));
        v2 = fminf(v2, __shfl_xor_sync(0xffffffffu, v2, o));
        v3 = fmaxf(v3, __shfl_xor_sync(0xffffffffu, v3, o));
    }
    int lane = j & 31, w = j >> 5;
    if (lane == 0) { red[0][w] = v0; red[1][w] = v1; red[2][w] = v2; red[3][w] = v3; }
    __syncthreads();
    if (j < 16) {
        float mn0 = red[0][j], mx0 = red[1][j], mn1 = red[2][j], mx1 = red[3][j];
        #pragma unroll
        for (int o = 8; o; o >>= 1) {
            mn0 = fminf(mn0, __shfl_xor_sync(0xffffu, mn0, o));
            mx0 = fmaxf(mx0, __shfl_xor_sync(0xffffu, mx0, o));
            mn1 = fminf(mn1, __shfl_xor_sync(0xffffu, mn1, o));
            mx1 = fmaxf(mx1, __shfl_xor_sync(0xffffu, mx1, o));
        }
        if (j == 0) {
            atomicMin(&d_minmax[b*4 + 0], __float_as_int(mn0));
            atomicMax(&d_minmax[b*4 + 1], __float_as_int(mx0));
            atomicMin(&d_minmax[b*4 + 2], __float_as_int(mn1));
            atomicMax(&d_minmax[b*4 + 3], __float_as_int(mx1));
        }
    }
}

// ---------------------------------------------------------------------------
// Accumulate: sdf normalize + boundary (pos^2==1) + sigmoid-sum product.
// ---------------------------------------------------------------------------
__device__ __forceinline__ float sigf(float x) {
    return __fdividef(1.0f, 1.0f + __expf(-x));
}

__global__ void accum_kernel(const float* __restrict__ yp, float* __restrict__ out) {
    __shared__ float sred[8];
    int b = blockIdx.y;
    float pmin2 = __int_as_float(d_minmax[b*4 + 0]);
    float pmax2 = __int_as_float(d_minmax[b*4 + 1]);
    float nmin2 = __int_as_float(d_minmax[b*4 + 2]);
    float nmax2 = __int_as_float(d_minmax[b*4 + 3]);
    bool any = (pmax2 > 0.0f);

    float acc = 0.0f;
    if (any) {
        float pmin = sqrtf(pmin2), pmax = sqrtf(pmax2);
        float nmin = sqrtf(nmin2), nmax = sqrtf(nmax2);
        float pr = 1.0f / (pmax - pmin);
        float nr = 1.0f / (nmax - nmin);
        float cst = pmin * pr - nmin * nr;

        int pix0 = (blockIdx.x * blockDim.x + threadIdx.x) * 4;
        const float4* dp = (const float4*)(d_dis2 + (size_t)b * NPIX + pix0);
        float4 dA = __ldg(dp);
        float4 dB = __ldg(dp + 1);

        float sdf0 = (dA.x == 1.0f) ? 0.0f : (sqrtf(dA.y)*nr - sqrtf(dA.x)*pr + cst);
        float sdf1 = (dA.z == 1.0f) ? 0.0f : (sqrtf(dA.w)*nr - sqrtf(dA.z)*pr + cst);
        float sdf2 = (dB.x == 1.0f) ? 0.0f : (sqrtf(dB.y)*nr - sqrtf(dB.x)*pr + cst);
        float sdf3 = (dB.z == 1.0f) ? 0.0f : (sqrtf(dB.w)*nr - sqrtf(dB.z)*pr + cst);

        float s0 = 0.f, s1 = 0.f, s2 = 0.f, s3 = 0.f;
        #pragma unroll
        for (int ch = 0; ch < CC; ch++) {
            const float4* ypp = (const float4*)(yp + ((size_t)(b*CC + ch) << 18) + pix0);
            float4 y = __ldg(ypp);
            s0 += sigf(y.x); s1 += sigf(y.y); s2 += sigf(y.z); s3 += sigf(y.w);
        }
        acc = sdf0*s0 + sdf1*s1 + sdf2*s2 + sdf3*s3;
    }

    #pragma unroll
    for (int o = 16; o; o >>= 1) acc += __shfl_xor_sync(0xffffffffu, acc, o);
    int lane = threadIdx.x & 31, w = threadIdx.x >> 5;
    if (lane == 0) sred[w] = acc;
    __syncthreads();
    if (threadIdx.x == 0) {
        float ba = 0.0f;
        #pragma unroll
        for (int k = 0; k < 8; k++) ba += sred[k];
        atomicAdd(&d_acc, (double)ba);
        __threadfence();
        int old = atomicAdd(&d_count, 1);
        int total = gridDim.x * gridDim.y;
        if (old == total - 1) {
            double t = atomicAdd(&d_acc, 0.0);
            out[0] = (float)(t / (double)((size_t)BB * CC * NPIX));
            d_acc = 0.0;
            d_count = 0;
        }
    }
}

extern "C" void kernel_launch(void* const* d_in, const int* in_sizes, int n_in,
                              void* d_out, int out_size) {
    const float* yp = (const float*)d_in[0];  // y_pred (8,4,512,512)
    const float* yt = (const float*)d_in[1];  // y_true (8,4,512,512)
    (void)in_sizes; (void)n_in; (void)out_size;

    col_kernel<<<BB*32, CPB*NSEG>>>(yt);
    row_kernel<<<BB*HH, WW>>>();
    accum_kernel<<<dim3(NPIX/1024, BB), 256>>>(yp, (float*)d_out);
}

// round 13
// speedup vs baseline: 4.8576x; 1.1967x over previous
#include <cuda_runtime.h>
#include <math.h>

#define BB 8
#define CC 4
#define HH 512
#define WW 512
#define NPIX (HH*WW)

#define SEG  16         // rows per thread in col pass
#define NSEG 32         // segments per column
#define CPB  32         // columns per block (CPB*NSEG == 1024 threads)

// Scratch (device globals; allocation in kernel_launch is forbidden)
static __device__ unsigned int d_gp[BB*NPIX];   // packed col g: pol0 lo16, pol1 hi16 (8 MB)
static __device__ int          d_minmax[BB*4];  // per b: pmin2,pmax2,nmin2,nmax2 (float bits)
static __device__ double       d_S[BB*3*4];     // per b: {S_pos,S_neg,S_one} x 4 slices

// ---------------------------------------------------------------------------
// Column pass. g[i] = min(i + prefmin(m[j]-j), -i + sufmin(m[j]+j)).
// Both polarities ride in one u32 (lo/hi halfword) via SIMD vmins2/vadd2/vsub2.
// All packed values stay within signed-16 range ([-511, 16895]).
// seg is warp-uniform (c = lane) -> carry loops have uniform trip counts.
// Block 0 also zero-inits the reduction scratch (read only by later kernels).
// ---------------------------------------------------------------------------
__global__ void __launch_bounds__(CPB*NSEG) col_kernel(const float* __restrict__ yt) {
    if (blockIdx.x == 0) {
        int t = threadIdx.x;
        if (t < BB*4) d_minmax[t] = (t & 1) ? 0 : 0x7F800000;
        if (t >= 64 && t < 64 + BB*3*4) d_S[t - 64] = 0.0;
    }

    __shared__ unsigned sA[NSEG][CPB], sB[NSEG][CPB];

    int b    = blockIdx.x >> 4;                 // 16 col-tiles per batch
    int c    = threadIdx.x & (CPB-1);
    int col  = ((blockIdx.x & 15) * CPB) + c;
    int seg  = threadIdx.x >> 5;                // warp-uniform
    int r0   = seg * SEG;

    const float* src = yt + ((size_t)(b*CC + 1) << 18) + col;

    // Phase 1: one read of the mask; packed segment mins of (m-r) and (m+r).
    unsigned mb = 0;
    unsigned PA = 0x40004000u, PB = 0x40004000u;   // 16384 per half
    #pragma unroll
    for (int j = 0; j < SEG; j++) {
        int r = r0 + j;
        float v = __ldg(src + (size_t)r * WW);
        int ism = (v != 0.0f);
        mb |= (unsigned)ism << j;
        unsigned pm = ism ? 0x00000400u : 0x04000000u;  // (m0 lo, m1 hi)
        unsigned rr = (unsigned)r | ((unsigned)r << 16);
        PA = __vmins2(PA, __vsub2(pm, rr));
        PB = __vmins2(PB, __vadd2(pm, rr));
    }
    sA[seg][c] = PA; sB[seg][c] = PB;
    __syncthreads();

    // Scalar carries (packed): prefix over earlier segs, suffix over later.
    unsigned cA = 0x40004000u, cB = 0x40004000u;
    for (int s = 0; s < seg; s++)      cA = __vmins2(cA, sA[s][c]);
    for (int s = seg+1; s < NSEG; s++) cB = __vmins2(cB, sB[s][c]);

    // Phase 2: forward prefix part, kept in registers.
    unsigned freg[SEG];
    unsigned rA = cA;
    #pragma unroll
    for (int j = 0; j < SEG; j++) {
        int r = r0 + j;
        unsigned pm = ((mb >> j) & 1) ? 0x00000400u : 0x04000000u;
        unsigned rr = (unsigned)r | ((unsigned)r << 16);
        rA = __vmins2(rA, __vsub2(pm, rr));
        freg[j] = __vadd2(rA, rr);
    }

    // Phase 3: backward suffix part; combine; single packed store.
    unsigned* gp = d_gp + (size_t)b * NPIX + col;
    unsigned rB = cB;
    #pragma unroll
    for (int j = SEG-1; j >= 0; j--) {
        int r = r0 + j;
        unsigned pm = ((mb >> j) & 1) ? 0x00000400u : 0x04000000u;
        unsigned rr = (unsigned)r | ((unsigned)r << 16);
        rB = __vmins2(rB, __vadd2(pm, rr));
        gp[(size_t)r * WW] = __vmins2(freg[j], __vsub2(rB, rr));
    }
}

// ---------------------------------------------------------------------------
// Row pass fused with accumulation. Exact pruned parabola min (a candidate at
// radius r contributes >= r^2, so fminf past the break point is a no-op ->
// the combined loop over both polarities is exact). Then per pixel:
//   boundary <=> pos^2 == 1 ; nonboundary contributes ssum*{pos, neg, 1}
// to per-batch sums (normalization constants applied later in fin_kernel).
// ---------------------------------------------------------------------------
__device__ __forceinline__ float sigf(float x) {
    return __fdividef(1.0f, 1.0f + __expf(-x));
}

__global__ void __launch_bounds__(WW) row_kernel(const float* __restrict__ yp) {
    __shared__ float2 s[WW];
    __shared__ float red[7][16];
    int b   = blockIdx.x >> 9;
    int row = blockIdx.x & 511;
    int j   = threadIdx.x;
    size_t base = (size_t)b * NPIX + (size_t)row * WW;

    unsigned g = d_gp[base + j];
    int g0 = (int)(g & 0xFFFFu);
    int g1 = (int)(g >> 16);
    float a0 = (float)(g0 * g0);
    float a1 = (float)(g1 * g1);
    s[j] = make_float2(a0, a1);
    __syncthreads();

    float best0 = a0, best1 = a1;
    for (int r = 1; r < WW; r++) {
        float r2 = (float)(r * r);
        if (r2 >= fmaxf(best0, best1)) break;
        int jl = j - r, jr = j + r;
        if (jl >= 0) {
            float2 v = s[jl];
            best0 = fminf(best0, v.x + r2);
            best1 = fminf(best1, v.y + r2);
        }
        if (jr < WW) {
            float2 v = s[jr];
            best0 = fminf(best0, v.x + r2);
            best1 = fminf(best1, v.y + r2);
        }
    }

    // Per-pixel contribution (exclude boundary pixels: pos^2 == 1).
    float pos = sqrtf(best0), neg = sqrtf(best1);
    const float* p = yp + ((size_t)(b*CC) << 18) + (size_t)row * WW + j;
    float ssum = sigf(__ldg(p)) + sigf(__ldg(p + NPIX)) +
                 sigf(__ldg(p + 2*NPIX)) + sigf(__ldg(p + 3*NPIX));
    bool nb = (best0 != 1.0f);
    float t1 = nb ? ssum * pos : 0.0f;
    float t2 = nb ? ssum * neg : 0.0f;
    float t3 = nb ? ssum       : 0.0f;

    // Block reduction of 7 values: min0,max0,min1,max1,t1,t2,t3
    float v0 = best0, v1 = best0, v2 = best1, v3 = best1;
    #pragma unroll
    for (int o = 16; o; o >>= 1) {
        v0 = fminf(v0, __shfl_xor_sync(0xffffffffu, v0, o));
        v1 = fmaxf(v1, __shfl_xor_sync(0xffffffffu, v1, o));
        v2 = fminf(v2, __shfl_xor_sync(0xffffffffu, v2, o));
        v3 = fmaxf(v3, __shfl_xor_sync(0xffffffffu, v3, o));
        t1 += __shfl_xor_sync(0xffffffffu, t1, o);
        t2 += __shfl_xor_sync(0xffffffffu, t2, o);
        t3 += __shfl_xor_sync(0xffffffffu, t3, o);
    }
    int lane = j & 31, w = j >> 5;
    if (lane == 0) {
        red[0][w] = v0; red[1][w] = v1; red[2][w] = v2; red[3][w] = v3;
        red[4][w] = t1; red[5][w] = t2; red[6][w] = t3;
    }
    __syncthreads();
    if (j < 32) {
        bool act = (j < 16);
        v0 = act ? red[0][j] : __int_as_float(0x7F800000);
        v1 = act ? red[1][j] : 0.0f;
        v2 = act ? red[2][j] : __int_as_float(0x7F800000);
        v3 = act ? red[3][j] : 0.0f;
        t1 = act ? red[4][j] : 0.0f;
        t2 = act ? red[5][j] : 0.0f;
        t3 = act ? red[6][j] : 0.0f;
        #pragma unroll
        for (int o = 8; o; o >>= 1) {
            v0 = fminf(v0, __shfl_xor_sync(0xffffffffu, v0, o));
            v1 = fmaxf(v1, __shfl_xor_sync(0xffffffffu, v1, o));
            v2 = fminf(v2, __shfl_xor_sync(0xffffffffu, v2, o));
            v3 = fmaxf(v3, __shfl_xor_sync(0xffffffffu, v3, o));
            t1 += __shfl_xor_sync(0xffffffffu, t1, o);
            t2 += __shfl_xor_sync(0xffffffffu, t2, o);
            t3 += __shfl_xor_sync(0xffffffffu, t3, o);
        }
        if (j == 0) {
            int sl = blockIdx.x & 3;
            atomicMin(&d_minmax[b*4 + 0], __float_as_int(v0));
            atomicMax(&d_minmax[b*4 + 1], __float_as_int(v1));
            atomicMin(&d_minmax[b*4 + 2], __float_as_int(v2));
            atomicMax(&d_minmax[b*4 + 3], __float_as_int(v3));
            atomicAdd(&d_S[(b*3 + 0)*4 + sl], (double)t1);
            atomicAdd(&d_S[(b*3 + 1)*4 + sl], (double)t2);
            atomicAdd(&d_S[(b*3 + 2)*4 + sl], (double)t3);
        }
    }
}

// ---------------------------------------------------------------------------
// Finalize: apply per-batch normalization constants, combine, write scalar.
// ---------------------------------------------------------------------------
__global__ void fin_kernel(float* __restrict__ out) {
    int b = threadIdx.x;            // lanes 0-7 carry real work
    double tb = 0.0;
    if (b < BB) {
        float pmax2 = __int_as_float(d_minmax[b*4 + 1]);
        if (pmax2 > 0.0f) {         // mask nonempty
            float pmin = sqrtf(__int_as_float(d_minmax[b*4 + 0]));
            float pmax = sqrtf(pmax2);
            float nmin = sqrtf(__int_as_float(d_minmax[b*4 + 2]));
            float nmax = sqrtf(__int_as_float(d_minmax[b*4 + 3]));
            float pr = 1.0f / (pmax - pmin);
            float nr = 1.0f / (nmax - nmin);
            float cst = pmin * pr - nmin * nr;
            double S1 = 0.0, S2 = 0.0, S3 = 0.0;
            #pragma unroll
            for (int sl = 0; sl < 4; sl++) {
                S1 += d_S[(b*3 + 0)*4 + sl];
                S2 += d_S[(b*3 + 1)*4 + sl];
                S3 += d_S[(b*3 + 2)*4 + sl];
            }
            tb = (double)nr * S2 - (double)pr * S1 + (double)cst * S3;
        }
    }
    #pragma unroll
    for (int o = 4; o; o >>= 1) tb += __shfl_xor_sync(0xffffffffu, tb, o);
    if (threadIdx.x == 0)
        out[0] = (float)(tb / (double)((size_t)BB * CC * NPIX));
}

extern "C" void kernel_launch(void* const* d_in, const int* in_sizes, int n_in,
                              void* d_out, int out_size) {
    const float* yp = (const float*)d_in[0];  // y_pred (8,4,512,512)
    const float* yt = (const float*)d_in[1];  // y_true (8,4,512,512)
    (void)in_sizes; (void)n_in; (void)out_size;

    col_kernel<<<BB*16, CPB*NSEG>>>(yt);
    row_kernel<<<BB*HH, WW>>>(yp);
    fin_kernel<<<1, 32>>>((float*)d_out);
}